// round 13
// baseline (speedup 1.0000x reference)
#include <cuda_runtime.h>
#include <cuda_fp16.h>
#include <math.h>
#include <stdint.h>

// Problem constants
#define BATCH 2
#define SEQ   2048
#define CDIM  2048
#define NHEAD 16
#define NKV   4
#define HEADD 128
#define GROUP (NHEAD / NKV)      // 4
#define ROWS  (BATCH * SEQ)      // 4096
#define KVC   (NKV * HEADD)      // 512
#define NCAT  (CDIM + KVC + KVC) // 3072

// Q pre-scale: (1/sqrt(128)) * log2(e)  -> softmax done in base-2 domain
#define QSCALE 0.12751743f

// Scratch (device globals; allocation is forbidden)
__device__ __align__(128) __half g_xh  [(size_t)ROWS * CDIM];
__device__ __align__(128) __half g_Qh  [(size_t)ROWS * CDIM];
__device__ __align__(128) __half g_Kh  [(size_t)ROWS * KVC];
__device__ __align__(128) __half g_Vt  [(size_t)KVC * ROWS];   // transposed V
__device__ __align__(128) __half g_Yh  [(size_t)ROWS * CDIM];
__device__ __align__(128) __half g_Wcat[(size_t)NCAT * CDIM];  // [Wq;Wk;Wv]^T K-major
__device__ __align__(128) __half g_WoT [(size_t)CDIM * CDIM];

__device__ __forceinline__ uint32_t smem_u32(const void* p) {
    uint32_t a;
    asm("{ .reg .u64 t; cvta.to.shared.u64 t, %1; cvt.u32.u64 %0, t; }"
        : "=r"(a) : "l"(p));
    return a;
}
__device__ __forceinline__ float ex2f(float x) {
    float y;
    asm("ex2.approx.f32 %0, %1;" : "=f"(y) : "f"(x));
    return y;
}
// pack two floats into one f16x2 word (lo = a, hi = b)
__device__ __forceinline__ uint32_t pack_h2(float a, float b) {
    uint32_t r;
    asm("cvt.rn.f16x2.f32 %0, %1, %2;" : "=r"(r) : "f"(b), "f"(a));
    return r;
}

#define MMA_F16(D, a0, a1, a2, a3, b0, b1)                                    \
    asm volatile(                                                             \
        "mma.sync.aligned.m16n8k16.row.col.f32.f16.f16.f32 "                  \
        "{%0,%1,%2,%3}, {%4,%5,%6,%7}, {%8,%9}, {%0,%1,%2,%3};"               \
        : "+f"(D[0]), "+f"(D[1]), "+f"(D[2]), "+f"(D[3])                      \
        : "r"(a0), "r"(a1), "r"(a2), "r"(a3), "r"(b0), "r"(b1))

#define LDSM4(r0, r1, r2, r3, addr)                                           \
    asm volatile("ldmatrix.sync.aligned.m8n8.x4.shared.b16 {%0,%1,%2,%3}, [%4];" \
                 : "=r"(r0), "=r"(r1), "=r"(r2), "=r"(r3) : "r"(addr))

#define CP_ASYNC16(saddr, gptr)                                               \
    asm volatile("cp.async.ca.shared.global [%0], [%1], 16;"                  \
                 :: "r"(saddr), "l"(gptr))
#define CP_COMMIT() asm volatile("cp.async.commit_group;" ::: "memory")
#define CP_WAIT0()  asm volatile("cp.async.wait_group 0;" ::: "memory")
#define CP_WAIT1()  asm volatile("cp.async.wait_group 1;" ::: "memory")

// ---------------------------------------------------------------------------
// x -> half
// ---------------------------------------------------------------------------
__global__ __launch_bounds__(256)
void cvt_half(const float* __restrict__ in, __half* __restrict__ out, int n4)
{
    int i = blockIdx.x * 256 + threadIdx.x;
    if (i < n4) {
        float4 v = *(const float4*)(in + (size_t)i * 4);
        __half2* o = (__half2*)(out + (size_t)i * 4);
        o[0] = __floats2half2_rn(v.x, v.y);
        o[1] = __floats2half2_rn(v.z, v.w);
    }
}

// ---------------------------------------------------------------------------
// Weight transpose + half: Wt[n][k] = half(W[k][n])
// ---------------------------------------------------------------------------
__global__ __launch_bounds__(256)
void transpose_half(const float* __restrict__ W, __half* __restrict__ Wt,
                    int Kdim, int N)
{
    __shared__ float tile[32][33];
    const int bx = blockIdx.x * 32;   // n
    const int by = blockIdx.y * 32;   // k
    const int tx = threadIdx.x & 31;
    const int ty = threadIdx.x >> 5;
#pragma unroll
    for (int i = ty; i < 32; i += 8)
        tile[i][tx] = W[(size_t)(by + i) * N + bx + tx];
    __syncthreads();
#pragma unroll
    for (int i = ty; i < 32; i += 8)
        Wt[(size_t)(bx + i) * Kdim + by + tx] = __float2half_rn(tile[tx][i]);
}

// ---------------------------------------------------------------------------
// fp16 tensor-core GEMM mainloop: C = A[M,K] @ Bt[N,K]^T.
// 128x128 tile, BK=32, 256 thr, 3-stage cp.async ring.
// Wait discipline: at iter c the newest committed chunk is min(c+1, NC-1);
// allowed pending = that minus c  ->  wait_group 1, except wait_group 0 on
// the FINAL iteration (R10 NaN bug: last chunk was read while in flight).
// MODE 2: float out. MODE 3: fused QKV epilogue.
// ---------------------------------------------------------------------------
#define GW 20                      // words per smem tile row (bank-safe)
#define GTILEW (128 * GW)          // words per tile
#define GSTAGES 3
#define GEMM_SMEM_BYTES (GSTAGES * 2 * GTILEW * 4)   // 61,440

template <int MODE>
__global__ __launch_bounds__(256)
void gemm_h(const __half* __restrict__ A, const __half* __restrict__ Bt,
            float* __restrict__ Cf, __half* __restrict__ Cq,
            __half* __restrict__ Ck, __half* __restrict__ Cvt,
            int M, int N, int Kdim)
{
    extern __shared__ uint32_t sm[];          // [stage][A,B][tile]
    const uint32_t smb = smem_u32(sm);

    const int tid  = threadIdx.x;
    const int wid  = tid >> 5;
    const int lane = tid & 31;
    const int g = lane >> 2;
    const int t = lane & 3;
    const int wr = (wid & 3) * 32;
    const int wc = (wid >> 2) * 64;
    const int bm = blockIdx.y * 128;
    const int bn = blockIdx.x * 128;

    // ldmatrix per-lane offsets (bytes within a tile)
    const int rA  = (lane & 7) + ((lane >> 3) & 1) * 8;
    const int kAw = (lane >> 4) * 4;
    const int rB  = (lane & 7) + (lane >> 4) * 8;
    const int kBw = ((lane >> 3) & 1) * 4;
    uint32_t offA[2], offB[4];
#pragma unroll
    for (int mt = 0; mt < 2; mt++)
        offA[mt] = (uint32_t)(((wr + mt * 16 + rA) * GW + kAw) * 4);
#pragma unroll
    for (int p = 0; p < 4; p++)
        offB[p] = (uint32_t)(((wc + 16 * p + rB) * GW + kBw) * 4);

    // cp.async load mapping
    const int lrow = tid >> 1;
    const int lch0 = (tid & 1) * 2;
    const __half* agp0 = A  + (size_t)(bm + lrow) * Kdim + lch0 * 8;
    const __half* bgp0 = Bt + (size_t)(bn + lrow) * Kdim + lch0 * 8;
    const uint32_t lofs = (uint32_t)(lrow * GW + lch0 * 4) * 4;

    float acc[2][8][4];
#pragma unroll
    for (int mt = 0; mt < 2; mt++)
#pragma unroll
        for (int nt = 0; nt < 8; nt++)
#pragma unroll
            for (int e = 0; e < 4; e++) acc[mt][nt][e] = 0.0f;

    const int NC = Kdim / 32;

    // prologue: chunks 0,1 into stages 0,1
#pragma unroll
    for (int pc = 0; pc < 2; pc++) {
        const uint32_t sb = smb + (uint32_t)(pc * 2 * GTILEW) * 4 + lofs;
        const __half* ag = agp0 + pc * 32;
        const __half* bg = bgp0 + pc * 32;
        CP_ASYNC16(sb,                   ag);
        CP_ASYNC16(sb + 16,              ag + 8);
        CP_ASYNC16(sb + GTILEW * 4,      bg);
        CP_ASYNC16(sb + GTILEW * 4 + 16, bg + 8);
        CP_COMMIT();
    }

    for (int c = 0; c < NC; c++) {
        const int s = c % GSTAGES;
        if (c + 1 < NC) { CP_WAIT1(); } else { CP_WAIT0(); }   // FIX: drain fully on last
        __syncthreads();

        if (c + 2 < NC) {
            const int sp = (c + 2) % GSTAGES;
            const uint32_t sb = smb + (uint32_t)(sp * 2 * GTILEW) * 4 + lofs;
            const __half* ag = agp0 + (c + 2) * 32;
            const __half* bg = bgp0 + (c + 2) * 32;
            CP_ASYNC16(sb,                   ag);
            CP_ASYNC16(sb + 16,              ag + 8);
            CP_ASYNC16(sb + GTILEW * 4,      bg);
            CP_ASYNC16(sb + GTILEW * 4 + 16, bg + 8);
            CP_COMMIT();
        }

        const uint32_t aBase = smb + (uint32_t)(s * 2 * GTILEW) * 4;
        const uint32_t bBase = aBase + GTILEW * 4;

#pragma unroll
        for (int ks = 0; ks < 2; ks++) {
            uint32_t a[2][4], bf[8][2];
            LDSM4(a[0][0], a[0][1], a[0][2], a[0][3], aBase + offA[0] + ks * 32);
            LDSM4(a[1][0], a[1][1], a[1][2], a[1][3], aBase + offA[1] + ks * 32);
#pragma unroll
            for (int p = 0; p < 4; p++)
                LDSM4(bf[2 * p][0], bf[2 * p][1], bf[2 * p + 1][0],
                      bf[2 * p + 1][1], bBase + offB[p] + ks * 32);
#pragma unroll
            for (int mt = 0; mt < 2; mt++)
#pragma unroll
                for (int nt = 0; nt < 8; nt++)
                    MMA_F16(acc[mt][nt], a[mt][0], a[mt][1], a[mt][2], a[mt][3],
                            bf[nt][0], bf[nt][1]);
        }
        // next iteration's syncthreads (after wait) fences stage reuse
    }

    // Epilogue
    if (MODE == 2) {
#pragma unroll
        for (int mt = 0; mt < 2; mt++) {
            int r = bm + wr + mt * 16 + g;
#pragma unroll
            for (int nt = 0; nt < 8; nt++) {
                int cc = bn + wc + 8 * nt + 2 * t;
                *(float2*)(Cf + (size_t)r * N + cc) =
                    make_float2(acc[mt][nt][0], acc[mt][nt][1]);
                *(float2*)(Cf + (size_t)(r + 8) * N + cc) =
                    make_float2(acc[mt][nt][2], acc[mt][nt][3]);
            }
        }
    } else {  // MODE 3: fused QKV split (branch is uniform per CTA)
        if (bn < CDIM) {
            __half2* C = (__half2*)Cq;
#pragma unroll
            for (int mt = 0; mt < 2; mt++) {
                int r = bm + wr + mt * 16 + g;
#pragma unroll
                for (int nt = 0; nt < 8; nt++) {
                    int cw = (bn + wc + 8 * nt + 2 * t) >> 1;
                    C[(size_t)r * (CDIM >> 1) + cw] = __floats2half2_rn(
                        acc[mt][nt][0] * QSCALE, acc[mt][nt][1] * QSCALE);
                    C[(size_t)(r + 8) * (CDIM >> 1) + cw] = __floats2half2_rn(
                        acc[mt][nt][2] * QSCALE, acc[mt][nt][3] * QSCALE);
                }
            }
        } else if (bn < CDIM + KVC) {
            __half2* C = (__half2*)Ck;
#pragma unroll
            for (int mt = 0; mt < 2; mt++) {
                int r = bm + wr + mt * 16 + g;
#pragma unroll
                for (int nt = 0; nt < 8; nt++) {
                    int cw = (bn - CDIM + wc + 8 * nt + 2 * t) >> 1;
                    C[(size_t)r * (KVC >> 1) + cw] =
                        __floats2half2_rn(acc[mt][nt][0], acc[mt][nt][1]);
                    C[(size_t)(r + 8) * (KVC >> 1) + cw] =
                        __floats2half2_rn(acc[mt][nt][2], acc[mt][nt][3]);
                }
            }
        } else {  // V: transposed half out, Cvt[N=512][ROWS]
#pragma unroll
            for (int mt = 0; mt < 2; mt++) {
                int m0 = bm + wr + mt * 16 + g;
#pragma unroll
                for (int nt = 0; nt < 8; nt++) {
                    int n0 = bn - (CDIM + KVC) + wc + 8 * nt + 2 * t;
                    Cvt[(size_t)n0 * ROWS + m0]           = __float2half_rn(acc[mt][nt][0]);
                    Cvt[(size_t)(n0 + 1) * ROWS + m0]     = __float2half_rn(acc[mt][nt][1]);
                    Cvt[(size_t)n0 * ROWS + m0 + 8]       = __float2half_rn(acc[mt][nt][2]);
                    Cvt[(size_t)(n0 + 1) * ROWS + m0 + 8] = __float2half_rn(acc[mt][nt][3]);
                }
            }
        }
    }
}

// ---------------------------------------------------------------------------
// fp16 flash attention, causal, GQA. 256 thr (8 warps x 16 q-rows, BQ=128).
// BKV=128: half the softmax/barrier events vs 64; with BQ==BKV only the LAST
// tile is diagonal, and on it warp-uniform guards skip all-masked MMAs.
// V tile is 128 rows x 128 keys = 256 B/row -> 16 chunks/row (R10 NaN bug:
// old mapping only filled 8).  cp.async double-buffered K/V stages.
// ---------------------------------------------------------------------------
#define BQ 128
#define BKV 128
#define QW 68
#define KW 68
#define VW 68
#define PW 68

#define KSTAGEW (BKV * KW)     // 8704
#define VSTAGEW (HEADD * VW)   // 8704
#define FLASH_SMEM_WORDS (BQ * QW + 2 * KSTAGEW + 2 * VSTAGEW + BQ * PW)
#define FLASH_SMEM_BYTES (FLASH_SMEM_WORDS * 4)   // 208,896

__global__ __launch_bounds__(256, 1)
void flash_h(const __half* __restrict__ Q, const __half* __restrict__ K,
             const __half* __restrict__ Vt, __half* __restrict__ Y)
{
    extern __shared__ uint32_t fsm[];
    uint32_t* Qs = fsm;                         // BQ x QW
    uint32_t* Ks = Qs + BQ * QW;                // 2 x KSTAGEW
    uint32_t* Vs = Ks + 2 * KSTAGEW;            // 2 x VSTAGEW
    uint32_t* Ps = Vs + 2 * VSTAGEW;            // BQ x PW
    const uint32_t qsb = smem_u32(Qs);
    const uint32_t ksb = smem_u32(Ks);
    const uint32_t vsb = smem_u32(Vs);
    const uint32_t psb = smem_u32(Ps);

    const int q0  = blockIdx.x * BQ;
    const int h   = blockIdx.y;
    const int b   = blockIdx.z;
    const int kvh = h / GROUP;
    const int tid  = threadIdx.x;
    const int wid  = tid >> 5;
    const int lane = tid & 31;
    const int g = lane >> 2;
    const int t = lane & 3;
    const int wr = wid * 16;

    // ldmatrix per-lane offsets
    const int rA  = (lane & 7) + ((lane >> 3) & 1) * 8;
    const int kAw = (lane >> 4) * 4;
    const int rB  = (lane & 7) + (lane >> 4) * 8;
    const int kBw = ((lane >> 3) & 1) * 4;
    const uint32_t offQ = (uint32_t)(((wr + rA) * QW + kAw) * 4);
    const uint32_t offP = (uint32_t)(((wr + rA) * PW + kAw) * 4);
    uint32_t offK[8], offV[8];
#pragma unroll
    for (int p = 0; p < 8; p++)
        offK[p] = (uint32_t)(((16 * p + rB) * KW + kBw) * 4);
#pragma unroll
    for (int p = 0; p < 8; p++)
        offV[p] = (uint32_t)(((16 * p + rB) * VW + kBw) * 4);

    // KV tile source mapping: both K and V tiles are 128 rows x 256 bytes
    // -> 16 chunks/row, 8 iterations of 16 rows per thread.
    const int rk  = tid >> 4, chk = tid & 15;
    const __half* Kbase0  = K  + (size_t)(b * SEQ) * KVC + kvh * HEADD;
    const __half* Vtbase0 = Vt + (size_t)(kvh * HEADD) * ROWS + b * SEQ;

    // Load Q tile (pre-scaled by QSCALE at projection time)
    const __half* Qbase = Q + (size_t)(b * SEQ + q0) * CDIM + h * HEADD;
#pragma unroll
    for (int i = 0; i < 8; i++) {
        int slot = tid + i * 256;
        int r = slot >> 4, ch = slot & 15;
        *(uint4*)(Qs + r * QW + ch * 4) =
            *(const uint4*)(Qbase + (size_t)r * CDIM + ch * 8);
    }

    float oa[16][4];
#pragma unroll
    for (int nt = 0; nt < 16; nt++)
#pragma unroll
        for (int e = 0; e < 4; e++) oa[nt][e] = 0.0f;
    float m0 = -1e30f, m1 = -1e30f, l0 = 0.0f, l1 = 0.0f;

    const int qrow0 = q0 + wr + g;
    const int qrow1 = qrow0 + 8;
    const int ntiles = blockIdx.x + 1;         // (q0 + BQ) / BKV

    // prologue: prefetch tile 0 into stage 0
#pragma unroll
    for (int i = 0; i < 8; i++) {
        int r = rk + i * 16;
        CP_ASYNC16(ksb + (uint32_t)((r * KW + chk * 4) * 4),
                   Kbase0 + (size_t)r * KVC + chk * 8);
        CP_ASYNC16(vsb + (uint32_t)((r * VW + chk * 4) * 4),
                   Vtbase0 + (size_t)r * ROWS + chk * 8);
    }
    CP_COMMIT();

    for (int tt = 0; tt < ntiles; tt++) {
        const int s = tt & 1;
        const bool diag = (tt == ntiles - 1);
        CP_WAIT0();
        __syncthreads();

        if (tt + 1 < ntiles) {
            const int k1 = (tt + 1) * BKV;
            const __half* Kb = Kbase0 + (size_t)k1 * KVC;
            const __half* Vb = Vtbase0 + k1;
            const uint32_t kd = ksb + (uint32_t)((1 - s) * KSTAGEW) * 4;
            const uint32_t vd = vsb + (uint32_t)((1 - s) * VSTAGEW) * 4;
#pragma unroll
            for (int i = 0; i < 8; i++) {
                int r = rk + i * 16;
                CP_ASYNC16(kd + (uint32_t)((r * KW + chk * 4) * 4),
                           Kb + (size_t)r * KVC + chk * 8);
                CP_ASYNC16(vd + (uint32_t)((r * VW + chk * 4) * 4),
                           Vb + (size_t)r * ROWS + chk * 8);
            }
            CP_COMMIT();
        }

        const uint32_t kBase = ksb + (uint32_t)(s * KSTAGEW) * 4;
        const uint32_t vBase = vsb + (uint32_t)(s * VSTAGEW) * 4;
        const int k0 = tt * BKV;

        // ---- S = Q @ K^T (warp: 16 x 128), 8 k16-steps over D=128 ----
        float sa[16][4];
#pragma unroll
        for (int j = 0; j < 16; j++)
#pragma unroll
            for (int e = 0; e < 4; e++) sa[j][e] = 0.0f;

#pragma unroll
        for (int ks = 0; ks < 8; ks++) {
            uint32_t a[4];
            LDSM4(a[0], a[1], a[2], a[3], qsb + offQ + ks * 32);
#pragma unroll
            for (int p = 0; p < 8; p++) {
                if (!diag || p <= wid) {    // warp-uniform: skip all-masked
                    uint32_t b0, b1, b2, b3;
                    LDSM4(b0, b1, b2, b3, kBase + offK[p] + ks * 32);
                    MMA_F16(sa[2 * p],     a[0], a[1], a[2], a[3], b0, b1);
                    MMA_F16(sa[2 * p + 1], a[0], a[1], a[2], a[3], b2, b3);
                }
            }
        }

        // ---- causal mask (diag tile only) + online softmax (base-2) ----
        float ml0 = -1e30f, ml1 = -1e30f;
        if (diag) {
#pragma unroll
            for (int j = 0; j < 16; j++)
#pragma unroll
                for (int e = 0; e < 2; e++) {
                    int key = k0 + 8 * j + 2 * t + e;
                    if (key > qrow0) sa[j][e]     = -1e30f;
                    if (key > qrow1) sa[j][2 + e] = -1e30f;
                    ml0 = fmaxf(ml0, sa[j][e]);
                    ml1 = fmaxf(ml1, sa[j][2 + e]);
                }
        } else {
#pragma unroll
            for (int j = 0; j < 16; j++) {
                ml0 = fmaxf(ml0, fmaxf(sa[j][0], sa[j][1]));
                ml1 = fmaxf(ml1, fmaxf(sa[j][2], sa[j][3]));
            }
        }
        ml0 = fmaxf(ml0, __shfl_xor_sync(0xffffffffu, ml0, 1));
        ml0 = fmaxf(ml0, __shfl_xor_sync(0xffffffffu, ml0, 2));
        ml1 = fmaxf(ml1, __shfl_xor_sync(0xffffffffu, ml1, 1));
        ml1 = fmaxf(ml1, __shfl_xor_sync(0xffffffffu, ml1, 2));

        float mn0 = fmaxf(m0, ml0), mn1 = fmaxf(m1, ml1);
        float corr0 = ex2f(m0 - mn0), corr1 = ex2f(m1 - mn1);
        m0 = mn0; m1 = mn1;

        float s0 = 0.0f, s1 = 0.0f;
#pragma unroll
        for (int j = 0; j < 16; j++) {
            float p00 = ex2f(sa[j][0] - mn0);
            float p01 = ex2f(sa[j][1] - mn0);
            float p10 = ex2f(sa[j][2] - mn1);
            float p11 = ex2f(sa[j][3] - mn1);
            s0 += p00 + p01;
            s1 += p10 + p11;
            Ps[(wr + g) * PW + 4 * j + t]     = pack_h2(p00, p01);
            Ps[(wr + 8 + g) * PW + 4 * j + t] = pack_h2(p10, p11);
        }
        s0 += __shfl_xor_sync(0xffffffffu, s0, 1);
        s0 += __shfl_xor_sync(0xffffffffu, s0, 2);
        s1 += __shfl_xor_sync(0xffffffffu, s1, 1);
        s1 += __shfl_xor_sync(0xffffffffu, s1, 2);
        l0 = l0 * corr0 + s0;
        l1 = l1 * corr1 + s1;

#pragma unroll
        for (int nt = 0; nt < 16; nt++) {
            oa[nt][0] *= corr0; oa[nt][1] *= corr0;
            oa[nt][2] *= corr1; oa[nt][3] *= corr1;
        }
        __syncwarp();

        // ---- O += P @ V (warp: 16 x 128), 8 k16-steps over BKV ----
#pragma unroll
        for (int ks = 0; ks < 8; ks++) {
            if (!diag || ks <= wid) {       // warp-uniform: P cols all zero
                uint32_t a[4];
                LDSM4(a[0], a[1], a[2], a[3], psb + offP + ks * 32);
#pragma unroll
                for (int p = 0; p < 8; p++) {
                    uint32_t b0, b1, b2, b3;
                    LDSM4(b0, b1, b2, b3, vBase + offV[p] + ks * 32);
                    MMA_F16(oa[2 * p],     a[0], a[1], a[2], a[3], b0, b1);
                    MMA_F16(oa[2 * p + 1], a[0], a[1], a[2], a[3], b2, b3);
                }
            }
        }
    }

    // ---- normalize + write Y (half) in (B,T,H,D) layout ----
    const float inv0 = 1.0f / l0, inv1 = 1.0f / l1;
    __half2* Yb = (__half2*)(Y + (size_t)(b * SEQ + q0 + wr) * CDIM + h * HEADD);
    const int wstr = CDIM >> 1;
#pragma unroll
    for (int nt = 0; nt < 16; nt++) {
        int cw = 4 * nt + t;
        Yb[(size_t)g * wstr + cw] =
            __floats2half2_rn(oa[nt][0] * inv0, oa[nt][1] * inv0);
        Yb[(size_t)(g + 8) * wstr + cw] =
            __floats2half2_rn(oa[nt][2] * inv1, oa[nt][3] * inv1);
    }
}

// ---------------------------------------------------------------------------
extern "C" void kernel_launch(void* const* d_in, const int* in_sizes, int n_in,
                              void* d_out, int out_size)
{
    const float* x  = (const float*)d_in[0];
    const float* Wq = (const float*)d_in[1];
    const float* Wk = (const float*)d_in[2];
    const float* Wv = (const float*)d_in[3];
    const float* Wo = (const float*)d_in[4];
    float* out = (float*)d_out;

    __half *xh, *Qh, *Kh, *Vt, *Yh, *Wcat, *WoT;
    cudaGetSymbolAddress((void**)&xh,   g_xh);
    cudaGetSymbolAddress((void**)&Qh,   g_Qh);
    cudaGetSymbolAddress((void**)&Kh,   g_Kh);
    cudaGetSymbolAddress((void**)&Vt,   g_Vt);
    cudaGetSymbolAddress((void**)&Yh,   g_Yh);
    cudaGetSymbolAddress((void**)&Wcat, g_Wcat);
    cudaGetSymbolAddress((void**)&WoT,  g_WoT);

    // Pre-pass: x -> half; weights -> transposed half (K-major), QKV concat
    cvt_half<<<(ROWS * CDIM / 4 + 255) / 256, 256>>>(x, xh, ROWS * CDIM / 4);
    transpose_half<<<dim3(CDIM / 32, CDIM / 32), 256>>>(Wq, Wcat, CDIM, CDIM);
    transpose_half<<<dim3(KVC / 32, CDIM / 32), 256>>>(
        Wk, Wcat + (size_t)CDIM * CDIM, CDIM, KVC);
    transpose_half<<<dim3(KVC / 32, CDIM / 32), 256>>>(
        Wv, Wcat + (size_t)(CDIM + KVC) * CDIM, CDIM, KVC);
    transpose_half<<<dim3(CDIM / 32, CDIM / 32), 256>>>(Wo, WoT, CDIM, CDIM);

    cudaFuncSetAttribute(gemm_h<3>, cudaFuncAttributeMaxDynamicSharedMemorySize,
                         GEMM_SMEM_BYTES);
    cudaFuncSetAttribute(gemm_h<2>, cudaFuncAttributeMaxDynamicSharedMemorySize,
                         GEMM_SMEM_BYTES);

    // Fused QKV projection (one GEMM over concatenated weights)
    gemm_h<3><<<dim3(NCAT / 128, ROWS / 128), 256, GEMM_SMEM_BYTES>>>(
        xh, Wcat, nullptr, Qh, Kh, Vt, ROWS, NCAT, CDIM);

    // Flash attention
    cudaFuncSetAttribute(flash_h, cudaFuncAttributeMaxDynamicSharedMemorySize,
                         FLASH_SMEM_BYTES);
    flash_h<<<dim3(SEQ / BQ, NHEAD, BATCH), 256, FLASH_SMEM_BYTES>>>(
        Qh, Kh, Vt, Yh);

    // Output projection (fp32 out)
    gemm_h<2><<<dim3(CDIM / 128, ROWS / 128), 256, GEMM_SMEM_BYTES>>>(
        Yh, WoT, out, nullptr, nullptr, nullptr, ROWS, CDIM, CDIM);
}

// round 14
// speedup vs baseline: 1.0434x; 1.0434x over previous
#include <cuda_runtime.h>
#include <cuda_fp16.h>
#include <math.h>
#include <stdint.h>

// Problem constants
#define BATCH 2
#define SEQ   2048
#define CDIM  2048
#define NHEAD 16
#define NKV   4
#define HEADD 128
#define GROUP (NHEAD / NKV)      // 4
#define ROWS  (BATCH * SEQ)      // 4096
#define KVC   (NKV * HEADD)      // 512
#define NCAT  (CDIM + KVC + KVC) // 3072

// Q pre-scale: (1/sqrt(128)) * log2(e)  -> softmax done in base-2 domain
#define QSCALE 0.12751743f

// Scratch (device globals; allocation is forbidden)
__device__ __align__(128) __half g_xh  [(size_t)ROWS * CDIM];
__device__ __align__(128) __half g_Qh  [(size_t)ROWS * CDIM];
__device__ __align__(128) __half g_Kh  [(size_t)ROWS * KVC];
__device__ __align__(128) __half g_Vt  [(size_t)KVC * ROWS];   // transposed V
__device__ __align__(128) __half g_Yh  [(size_t)ROWS * CDIM];
__device__ __align__(128) __half g_Wcat[(size_t)NCAT * CDIM];  // [Wq;Wk;Wv]^T K-major
__device__ __align__(128) __half g_WoT [(size_t)CDIM * CDIM];

__device__ __forceinline__ uint32_t smem_u32(const void* p) {
    uint32_t a;
    asm("{ .reg .u64 t; cvta.to.shared.u64 t, %1; cvt.u32.u64 %0, t; }"
        : "=r"(a) : "l"(p));
    return a;
}
__device__ __forceinline__ float ex2f(float x) {
    float y;
    asm("ex2.approx.f32 %0, %1;" : "=f"(y) : "f"(x));
    return y;
}
// pack two floats into one f16x2 word (lo = a, hi = b)
__device__ __forceinline__ uint32_t pack_h2(float a, float b) {
    uint32_t r;
    asm("cvt.rn.f16x2.f32 %0, %1, %2;" : "=r"(r) : "f"(b), "f"(a));
    return r;
}

#define MMA_F16(D, a0, a1, a2, a3, b0, b1)                                    \
    asm volatile(                                                             \
        "mma.sync.aligned.m16n8k16.row.col.f32.f16.f16.f32 "                  \
        "{%0,%1,%2,%3}, {%4,%5,%6,%7}, {%8,%9}, {%0,%1,%2,%3};"               \
        : "+f"(D[0]), "+f"(D[1]), "+f"(D[2]), "+f"(D[3])                      \
        : "r"(a0), "r"(a1), "r"(a2), "r"(a3), "r"(b0), "r"(b1))

#define LDSM4(r0, r1, r2, r3, addr)                                           \
    asm volatile("ldmatrix.sync.aligned.m8n8.x4.shared.b16 {%0,%1,%2,%3}, [%4];" \
                 : "=r"(r0), "=r"(r1), "=r"(r2), "=r"(r3) : "r"(addr))

#define CP_ASYNC16(saddr, gptr)                                               \
    asm volatile("cp.async.ca.shared.global [%0], [%1], 16;"                  \
                 :: "r"(saddr), "l"(gptr))
#define CP_COMMIT() asm volatile("cp.async.commit_group;" ::: "memory")
#define CP_WAIT0()  asm volatile("cp.async.wait_group 0;" ::: "memory")

// ---------------------------------------------------------------------------
// x -> half
// ---------------------------------------------------------------------------
__global__ __launch_bounds__(256)
void cvt_half(const float* __restrict__ in, __half* __restrict__ out, int n4)
{
    int i = blockIdx.x * 256 + threadIdx.x;
    if (i < n4) {
        float4 v = *(const float4*)(in + (size_t)i * 4);
        __half2* o = (__half2*)(out + (size_t)i * 4);
        o[0] = __floats2half2_rn(v.x, v.y);
        o[1] = __floats2half2_rn(v.z, v.w);
    }
}

// ---------------------------------------------------------------------------
// Weight transpose + half: Wt[n][k] = half(W[k][n])
// ---------------------------------------------------------------------------
__global__ __launch_bounds__(256)
void transpose_half(const float* __restrict__ W, __half* __restrict__ Wt,
                    int Kdim, int N)
{
    __shared__ float tile[32][33];
    const int bx = blockIdx.x * 32;   // n
    const int by = blockIdx.y * 32;   // k
    const int tx = threadIdx.x & 31;
    const int ty = threadIdx.x >> 5;
#pragma unroll
    for (int i = ty; i < 32; i += 8)
        tile[i][tx] = W[(size_t)(by + i) * N + bx + tx];
    __syncthreads();
#pragma unroll
    for (int i = ty; i < 32; i += 8)
        Wt[(size_t)(bx + i) * Kdim + by + tx] = __float2half_rn(tile[tx][i]);
}

// ---------------------------------------------------------------------------
// fp16 tensor-core GEMM mainloop: C = A[M,K] @ Bt[N,K]^T.
// 128x128 tile, BK=32, 256 thr, cp.async double-buffered (R9 config — the
// 3-stage ring was measured neutral), ldmatrix fragments.
// MODE 2: float out. MODE 3: fused QKV epilogue.
// ---------------------------------------------------------------------------
#define GW 20                      // words per smem tile row (bank-safe)
#define GTILEW (128 * GW)          // words per tile

template <int MODE>
__global__ __launch_bounds__(256)
void gemm_h(const __half* __restrict__ A, const __half* __restrict__ Bt,
            float* __restrict__ Cf, __half* __restrict__ Cq,
            __half* __restrict__ Ck, __half* __restrict__ Cvt,
            int M, int N, int Kdim)
{
    __shared__ uint32_t sm[2 * 2 * GTILEW];   // [stage][A,B][tile]
    const uint32_t smb = smem_u32(sm);

    const int tid  = threadIdx.x;
    const int wid  = tid >> 5;
    const int lane = tid & 31;
    const int g = lane >> 2;
    const int t = lane & 3;
    const int wr = (wid & 3) * 32;
    const int wc = (wid >> 2) * 64;
    const int bm = blockIdx.y * 128;
    const int bn = blockIdx.x * 128;

    // ldmatrix per-lane offsets (bytes within a tile)
    const int rA  = (lane & 7) + ((lane >> 3) & 1) * 8;
    const int kAw = (lane >> 4) * 4;
    const int rB  = (lane & 7) + (lane >> 4) * 8;
    const int kBw = ((lane >> 3) & 1) * 4;
    uint32_t offA[2], offB[4];
#pragma unroll
    for (int mt = 0; mt < 2; mt++)
        offA[mt] = (uint32_t)(((wr + mt * 16 + rA) * GW + kAw) * 4);
#pragma unroll
    for (int p = 0; p < 4; p++)
        offB[p] = (uint32_t)(((wc + 16 * p + rB) * GW + kBw) * 4);

    // cp.async load mapping
    const int lrow = tid >> 1;
    const int lch0 = (tid & 1) * 2;
    const __half* agp0 = A  + (size_t)(bm + lrow) * Kdim + lch0 * 8;
    const __half* bgp0 = Bt + (size_t)(bn + lrow) * Kdim + lch0 * 8;
    const uint32_t sa0 = smb + (uint32_t)(lrow * GW + lch0 * 4) * 4;

    float acc[2][8][4];
#pragma unroll
    for (int mt = 0; mt < 2; mt++)
#pragma unroll
        for (int nt = 0; nt < 8; nt++)
#pragma unroll
            for (int e = 0; e < 4; e++) acc[mt][nt][e] = 0.0f;

    const int NC = Kdim / 32;

    // preload chunk 0 into stage 0
    CP_ASYNC16(sa0,                  agp0);
    CP_ASYNC16(sa0 + 16,             agp0 + 8);
    CP_ASYNC16(sa0 + GTILEW * 4,     bgp0);
    CP_ASYNC16(sa0 + GTILEW * 4 + 16, bgp0 + 8);
    CP_COMMIT();

    for (int c = 0; c < NC; c++) {
        const int s = c & 1;
        CP_WAIT0();
        __syncthreads();

        if (c + 1 < NC) {
            const uint32_t sb = sa0 + (uint32_t)((1 - s) * 2 * GTILEW) * 4;
            const __half* ag = agp0 + (c + 1) * 32;
            const __half* bg = bgp0 + (c + 1) * 32;
            CP_ASYNC16(sb,                  ag);
            CP_ASYNC16(sb + 16,             ag + 8);
            CP_ASYNC16(sb + GTILEW * 4,     bg);
            CP_ASYNC16(sb + GTILEW * 4 + 16, bg + 8);
            CP_COMMIT();
        }

        const uint32_t aBase = smb + (uint32_t)(s * 2 * GTILEW) * 4;
        const uint32_t bBase = aBase + GTILEW * 4;

#pragma unroll
        for (int ks = 0; ks < 2; ks++) {
            uint32_t a[2][4], bf[8][2];
            LDSM4(a[0][0], a[0][1], a[0][2], a[0][3], aBase + offA[0] + ks * 32);
            LDSM4(a[1][0], a[1][1], a[1][2], a[1][3], aBase + offA[1] + ks * 32);
#pragma unroll
            for (int p = 0; p < 4; p++)
                LDSM4(bf[2 * p][0], bf[2 * p][1], bf[2 * p + 1][0],
                      bf[2 * p + 1][1], bBase + offB[p] + ks * 32);
#pragma unroll
            for (int mt = 0; mt < 2; mt++)
#pragma unroll
                for (int nt = 0; nt < 8; nt++)
                    MMA_F16(acc[mt][nt], a[mt][0], a[mt][1], a[mt][2], a[mt][3],
                            bf[nt][0], bf[nt][1]);
        }
        __syncthreads();
    }

    // Epilogue
    if (MODE == 2) {
#pragma unroll
        for (int mt = 0; mt < 2; mt++) {
            int r = bm + wr + mt * 16 + g;
#pragma unroll
            for (int nt = 0; nt < 8; nt++) {
                int cc = bn + wc + 8 * nt + 2 * t;
                *(float2*)(Cf + (size_t)r * N + cc) =
                    make_float2(acc[mt][nt][0], acc[mt][nt][1]);
                *(float2*)(Cf + (size_t)(r + 8) * N + cc) =
                    make_float2(acc[mt][nt][2], acc[mt][nt][3]);
            }
        }
    } else {  // MODE 3: fused QKV split (branch is uniform per CTA)
        if (bn < CDIM) {
            __half2* C = (__half2*)Cq;
#pragma unroll
            for (int mt = 0; mt < 2; mt++) {
                int r = bm + wr + mt * 16 + g;
#pragma unroll
                for (int nt = 0; nt < 8; nt++) {
                    int cw = (bn + wc + 8 * nt + 2 * t) >> 1;
                    C[(size_t)r * (CDIM >> 1) + cw] = __floats2half2_rn(
                        acc[mt][nt][0] * QSCALE, acc[mt][nt][1] * QSCALE);
                    C[(size_t)(r + 8) * (CDIM >> 1) + cw] = __floats2half2_rn(
                        acc[mt][nt][2] * QSCALE, acc[mt][nt][3] * QSCALE);
                }
            }
        } else if (bn < CDIM + KVC) {
            __half2* C = (__half2*)Ck;
#pragma unroll
            for (int mt = 0; mt < 2; mt++) {
                int r = bm + wr + mt * 16 + g;
#pragma unroll
                for (int nt = 0; nt < 8; nt++) {
                    int cw = (bn - CDIM + wc + 8 * nt + 2 * t) >> 1;
                    C[(size_t)r * (KVC >> 1) + cw] =
                        __floats2half2_rn(acc[mt][nt][0], acc[mt][nt][1]);
                    C[(size_t)(r + 8) * (KVC >> 1) + cw] =
                        __floats2half2_rn(acc[mt][nt][2], acc[mt][nt][3]);
                }
            }
        } else {  // V: transposed half out, Cvt[N=512][ROWS]
#pragma unroll
            for (int mt = 0; mt < 2; mt++) {
                int m0 = bm + wr + mt * 16 + g;
#pragma unroll
                for (int nt = 0; nt < 8; nt++) {
                    int n0 = bn - (CDIM + KVC) + wc + 8 * nt + 2 * t;
                    Cvt[(size_t)n0 * ROWS + m0]           = __float2half_rn(acc[mt][nt][0]);
                    Cvt[(size_t)(n0 + 1) * ROWS + m0]     = __float2half_rn(acc[mt][nt][1]);
                    Cvt[(size_t)n0 * ROWS + m0 + 8]       = __float2half_rn(acc[mt][nt][2]);
                    Cvt[(size_t)(n0 + 1) * ROWS + m0 + 8] = __float2half_rn(acc[mt][nt][3]);
                }
            }
        }
    }
}

// ---------------------------------------------------------------------------
// fp16 flash attention, causal, GQA. 256 thr (8 warps x 16 q-rows, BQ=128).
// BKV=64 (R9 config). P kept REGISTER-RESIDENT for PV: the m16n8 S-accum
// layout equals the m16n8k16 A-fragment layout, so P fragments are built
// with cvt.rn.f16x2 packs — no smem store, no ldmatrix, no syncwarp.
// cp.async double-buffered K/V stages, ex2 softmax (Q pre-scaled).
// ---------------------------------------------------------------------------
#define BQ 128
#define BKV 64
#define QW 68
#define KW 68
#define VW 36

#define KSTAGEW (BKV * KW)     // 4352
#define VSTAGEW (HEADD * VW)   // 4608
#define FLASH_SMEM_WORDS (BQ * QW + 2 * KSTAGEW + 2 * VSTAGEW)
#define FLASH_SMEM_BYTES (FLASH_SMEM_WORDS * 4)   // 106,496

__global__ __launch_bounds__(256, 1)
void flash_h(const __half* __restrict__ Q, const __half* __restrict__ K,
             const __half* __restrict__ Vt, __half* __restrict__ Y)
{
    extern __shared__ uint32_t fsm[];
    uint32_t* Qs = fsm;                         // BQ x QW
    uint32_t* Ks = Qs + BQ * QW;                // 2 x KSTAGEW
    uint32_t* Vs = Ks + 2 * KSTAGEW;            // 2 x VSTAGEW
    const uint32_t qsb = smem_u32(Qs);
    const uint32_t ksb = smem_u32(Ks);
    const uint32_t vsb = smem_u32(Vs);

    const int q0  = blockIdx.x * BQ;
    const int h   = blockIdx.y;
    const int b   = blockIdx.z;
    const int kvh = h / GROUP;
    const int tid  = threadIdx.x;
    const int wid  = tid >> 5;
    const int lane = tid & 31;
    const int g = lane >> 2;
    const int t = lane & 3;
    const int wr = wid * 16;

    // ldmatrix per-lane offsets
    const int rA  = (lane & 7) + ((lane >> 3) & 1) * 8;
    const int kAw = (lane >> 4) * 4;
    const int rB  = (lane & 7) + (lane >> 4) * 8;
    const int kBw = ((lane >> 3) & 1) * 4;
    const uint32_t offQ = (uint32_t)(((wr + rA) * QW + kAw) * 4);
    uint32_t offK[4], offV[8];
#pragma unroll
    for (int p = 0; p < 4; p++)
        offK[p] = (uint32_t)(((16 * p + rB) * KW + kBw) * 4);
#pragma unroll
    for (int p = 0; p < 8; p++)
        offV[p] = (uint32_t)(((16 * p + rB) * VW + kBw) * 4);

    // KV tile source mapping (per-thread chunk mapping)
    const int rk  = tid >> 4, chk = tid & 15;      // K: 64 rows x 16 chunks / 4 iters
    const int rv  = tid >> 3, chv = tid & 7;       // V: 128 rows x 8 chunks / 4 iters
    const __half* Kbase0  = K  + (size_t)(b * SEQ) * KVC + kvh * HEADD;
    const __half* Vtbase0 = Vt + (size_t)(kvh * HEADD) * ROWS + b * SEQ;

    // Load Q tile (pre-scaled by QSCALE at projection time)
    const __half* Qbase = Q + (size_t)(b * SEQ + q0) * CDIM + h * HEADD;
#pragma unroll
    for (int i = 0; i < 8; i++) {
        int slot = tid + i * 256;
        int r = slot >> 4, ch = slot & 15;
        *(uint4*)(Qs + r * QW + ch * 4) =
            *(const uint4*)(Qbase + (size_t)r * CDIM + ch * 8);
    }

    float oa[16][4];
#pragma unroll
    for (int nt = 0; nt < 16; nt++)
#pragma unroll
        for (int e = 0; e < 4; e++) oa[nt][e] = 0.0f;
    float m0 = -1e30f, m1 = -1e30f, l0 = 0.0f, l1 = 0.0f;

    const int qrow0 = q0 + wr + g;
    const int qrow1 = qrow0 + 8;
    const int ntiles = q0 / BKV + 2;

    // prologue: prefetch tile 0 into stage 0
    {
#pragma unroll
        for (int i = 0; i < 4; i++) {
            int rki = rk + i * 16, rvi = rv + i * 32;
            CP_ASYNC16(ksb + (uint32_t)((rki * KW + chk * 4) * 4),
                       Kbase0 + (size_t)rki * KVC + chk * 8);
            CP_ASYNC16(vsb + (uint32_t)((rvi * VW + chv * 4) * 4),
                       Vtbase0 + (size_t)rvi * ROWS + chv * 8);
        }
        CP_COMMIT();
    }

    for (int tt = 0; tt < ntiles; tt++) {
        const int s = tt & 1;
        CP_WAIT0();
        __syncthreads();

        if (tt + 1 < ntiles) {
            const int k1 = (tt + 1) * BKV;
            const __half* Kb = Kbase0 + (size_t)k1 * KVC;
            const __half* Vb = Vtbase0 + k1;
            const uint32_t kd = ksb + (uint32_t)((1 - s) * KSTAGEW) * 4;
            const uint32_t vd = vsb + (uint32_t)((1 - s) * VSTAGEW) * 4;
#pragma unroll
            for (int i = 0; i < 4; i++) {
                int rki = rk + i * 16, rvi = rv + i * 32;
                CP_ASYNC16(kd + (uint32_t)((rki * KW + chk * 4) * 4),
                           Kb + (size_t)rki * KVC + chk * 8);
                CP_ASYNC16(vd + (uint32_t)((rvi * VW + chv * 4) * 4),
                           Vb + (size_t)rvi * ROWS + chv * 8);
            }
            CP_COMMIT();
        }

        const uint32_t kBase = ksb + (uint32_t)(s * KSTAGEW) * 4;
        const uint32_t vBase = vsb + (uint32_t)(s * VSTAGEW) * 4;
        const int k0 = tt * BKV;

        // ---- S = Q @ K^T (warp: 16 x 64), 8 k16-steps over D=128 ----
        float sa[8][4];
#pragma unroll
        for (int j = 0; j < 8; j++)
#pragma unroll
            for (int e = 0; e < 4; e++) sa[j][e] = 0.0f;

#pragma unroll
        for (int ks = 0; ks < 8; ks++) {
            uint32_t a[4], bf[8][2];
            LDSM4(a[0], a[1], a[2], a[3], qsb + offQ + ks * 32);
#pragma unroll
            for (int p = 0; p < 4; p++)
                LDSM4(bf[2 * p][0], bf[2 * p][1], bf[2 * p + 1][0],
                      bf[2 * p + 1][1], kBase + offK[p] + ks * 32);
#pragma unroll
            for (int j = 0; j < 8; j++)
                MMA_F16(sa[j], a[0], a[1], a[2], a[3], bf[j][0], bf[j][1]);
        }

        // ---- causal mask + online softmax (base-2 domain) ----
        float ml0 = -1e30f, ml1 = -1e30f;
#pragma unroll
        for (int j = 0; j < 8; j++)
#pragma unroll
            for (int e = 0; e < 2; e++) {
                int key = k0 + 8 * j + 2 * t + e;
                if (key > qrow0) sa[j][e]     = -1e30f;
                if (key > qrow1) sa[j][2 + e] = -1e30f;
                ml0 = fmaxf(ml0, sa[j][e]);
                ml1 = fmaxf(ml1, sa[j][2 + e]);
            }
        ml0 = fmaxf(ml0, __shfl_xor_sync(0xffffffffu, ml0, 1));
        ml0 = fmaxf(ml0, __shfl_xor_sync(0xffffffffu, ml0, 2));
        ml1 = fmaxf(ml1, __shfl_xor_sync(0xffffffffu, ml1, 1));
        ml1 = fmaxf(ml1, __shfl_xor_sync(0xffffffffu, ml1, 2));

        float mn0 = fmaxf(m0, ml0), mn1 = fmaxf(m1, ml1);
        float corr0 = ex2f(m0 - mn0), corr1 = ex2f(m1 - mn1);
        m0 = mn0; m1 = mn1;

        // p values overwrite sa in place (register-resident P)
        float s0 = 0.0f, s1 = 0.0f;
#pragma unroll
        for (int j = 0; j < 8; j++) {
            float p00 = ex2f(sa[j][0] - mn0);
            float p01 = ex2f(sa[j][1] - mn0);
            float p10 = ex2f(sa[j][2] - mn1);
            float p11 = ex2f(sa[j][3] - mn1);
            s0 += p00 + p01;
            s1 += p10 + p11;
            sa[j][0] = p00; sa[j][1] = p01;
            sa[j][2] = p10; sa[j][3] = p11;
        }
        s0 += __shfl_xor_sync(0xffffffffu, s0, 1);
        s0 += __shfl_xor_sync(0xffffffffu, s0, 2);
        s1 += __shfl_xor_sync(0xffffffffu, s1, 1);
        s1 += __shfl_xor_sync(0xffffffffu, s1, 2);
        l0 = l0 * corr0 + s0;
        l1 = l1 * corr1 + s1;

#pragma unroll
        for (int nt = 0; nt < 16; nt++) {
            oa[nt][0] *= corr0; oa[nt][1] *= corr0;
            oa[nt][2] *= corr1; oa[nt][3] *= corr1;
        }

        // ---- O += P @ V (warp: 16 x 128), 4 k16-steps over BKV ----
        // A-fragments built directly from the S/P accumulator registers:
        // frag(ks): a0 = (p[2ks][0], p[2ks][1])   -> row g,   keys 16ks+2t..+1
        //           a1 = (p[2ks][2], p[2ks][3])   -> row g+8
        //           a2 = (p[2ks+1][0], p[2ks+1][1]) -> row g,  keys 16ks+8+2t
        //           a3 = (p[2ks+1][2], p[2ks+1][3]) -> row g+8
#pragma unroll
        for (int ks = 0; ks < 4; ks++) {
            uint32_t a0 = pack_h2(sa[2 * ks][0],     sa[2 * ks][1]);
            uint32_t a1 = pack_h2(sa[2 * ks][2],     sa[2 * ks][3]);
            uint32_t a2 = pack_h2(sa[2 * ks + 1][0], sa[2 * ks + 1][1]);
            uint32_t a3 = pack_h2(sa[2 * ks + 1][2], sa[2 * ks + 1][3]);
#pragma unroll
            for (int p = 0; p < 8; p++) {
                uint32_t b0, b1, b2, b3;
                LDSM4(b0, b1, b2, b3, vBase + offV[p] + ks * 32);
                MMA_F16(oa[2 * p],     a0, a1, a2, a3, b0, b1);
                MMA_F16(oa[2 * p + 1], a0, a1, a2, a3, b2, b3);
            }
        }
    }

    // ---- normalize + write Y (half) in (B,T,H,D) layout ----
    const float inv0 = 1.0f / l0, inv1 = 1.0f / l1;
    __half2* Yb = (__half2*)(Y + (size_t)(b * SEQ + q0 + wr) * CDIM + h * HEADD);
    const int wstr = CDIM >> 1;
#pragma unroll
    for (int nt = 0; nt < 16; nt++) {
        int cw = 4 * nt + t;
        Yb[(size_t)g * wstr + cw] =
            __floats2half2_rn(oa[nt][0] * inv0, oa[nt][1] * inv0);
        Yb[(size_t)(g + 8) * wstr + cw] =
            __floats2half2_rn(oa[nt][2] * inv1, oa[nt][3] * inv1);
    }
}

// ---------------------------------------------------------------------------
extern "C" void kernel_launch(void* const* d_in, const int* in_sizes, int n_in,
                              void* d_out, int out_size)
{
    const float* x  = (const float*)d_in[0];
    const float* Wq = (const float*)d_in[1];
    const float* Wk = (const float*)d_in[2];
    const float* Wv = (const float*)d_in[3];
    const float* Wo = (const float*)d_in[4];
    float* out = (float*)d_out;

    __half *xh, *Qh, *Kh, *Vt, *Yh, *Wcat, *WoT;
    cudaGetSymbolAddress((void**)&xh,   g_xh);
    cudaGetSymbolAddress((void**)&Qh,   g_Qh);
    cudaGetSymbolAddress((void**)&Kh,   g_Kh);
    cudaGetSymbolAddress((void**)&Vt,   g_Vt);
    cudaGetSymbolAddress((void**)&Yh,   g_Yh);
    cudaGetSymbolAddress((void**)&Wcat, g_Wcat);
    cudaGetSymbolAddress((void**)&WoT,  g_WoT);

    // Pre-pass: x -> half; weights -> transposed half (K-major), QKV concat
    cvt_half<<<(ROWS * CDIM / 4 + 255) / 256, 256>>>(x, xh, ROWS * CDIM / 4);
    transpose_half<<<dim3(CDIM / 32, CDIM / 32), 256>>>(Wq, Wcat, CDIM, CDIM);
    transpose_half<<<dim3(KVC / 32, CDIM / 32), 256>>>(
        Wk, Wcat + (size_t)CDIM * CDIM, CDIM, KVC);
    transpose_half<<<dim3(KVC / 32, CDIM / 32), 256>>>(
        Wv, Wcat + (size_t)(CDIM + KVC) * CDIM, CDIM, KVC);
    transpose_half<<<dim3(CDIM / 32, CDIM / 32), 256>>>(Wo, WoT, CDIM, CDIM);

    // Fused QKV projection (one GEMM over concatenated weights)
    gemm_h<3><<<dim3(NCAT / 128, ROWS / 128), 256>>>(
        xh, Wcat, nullptr, Qh, Kh, Vt, ROWS, NCAT, CDIM);

    // Flash attention
    cudaFuncSetAttribute(flash_h, cudaFuncAttributeMaxDynamicSharedMemorySize,
                         FLASH_SMEM_BYTES);
    flash_h<<<dim3(SEQ / BQ, NHEAD, BATCH), 256, FLASH_SMEM_BYTES>>>(
        Qh, Kh, Vt, Yh);

    // Output projection (fp32 out)
    gemm_h<2><<<dim3(CDIM / 128, ROWS / 128), 256>>>(
        Yh, WoT, out, nullptr, nullptr, nullptr, ROWS, CDIM, CDIM);
}